// round 1
// baseline (speedup 1.0000x reference)
#include <cuda_runtime.h>
#include <cuda_bf16.h>
#include <math.h>

#define NPTS 16384
#define C 512
#define H 8
#define HD 64
#define KWIN 1024
#define P (NPTS / KWIN)
#define SCALE 0.125f

// ---------------- scratch (device globals; no allocation allowed) ----------------
__device__ float g_tmp1[NPTS * C];      // h0 (cpe conv out) / feat2
__device__ float g_tmp2[NPTS * C];      // h1 (cpe_lin out)
__device__ float g_feat1[NPTS * C];     // feat after CPE residual
__device__ float g_x[NPTS * C];         // LN output
__device__ float g_qkv[NPTS * 3 * C];   // qkv
__device__ float g_o[NPTS * C];         // attention output (unserialized)
__device__ float g_y[NPTS * 4 * C];     // fc1 output

// ---------------- generic tiled SGEMM: out = act(A @ B^T + bias) (+res) ----------
// A: [M,Kk] row-major, B: [Nn,Kk] row-major, out: [M,Nn]
template <bool GELU, bool RES>
__global__ void sgemm_kernel(const float* __restrict__ A, const float* __restrict__ B,
                             const float* __restrict__ bias, const float* __restrict__ res,
                             float* __restrict__ out, int M, int Nn, int Kk)
{
    __shared__ float As[16][68];
    __shared__ float Bs[16][68];
    const int bm = blockIdx.y * 64, bn = blockIdx.x * 64;
    const int t = threadIdx.x;          // 256
    const int lrow = t >> 2, lseg = t & 3;
    const int tm = t >> 4, tn = t & 15;
    float acc[4][4] = {};

    const float* Ap = A + (size_t)(bm + lrow) * Kk + lseg * 4;
    const float* Bp = B + (size_t)(bn + lrow) * Kk + lseg * 4;

    for (int k0 = 0; k0 < Kk; k0 += 16) {
        float4 a = *(const float4*)(Ap + k0);
        float4 b = *(const float4*)(Bp + k0);
        As[lseg * 4 + 0][lrow] = a.x; As[lseg * 4 + 1][lrow] = a.y;
        As[lseg * 4 + 2][lrow] = a.z; As[lseg * 4 + 3][lrow] = a.w;
        Bs[lseg * 4 + 0][lrow] = b.x; Bs[lseg * 4 + 1][lrow] = b.y;
        Bs[lseg * 4 + 2][lrow] = b.z; Bs[lseg * 4 + 3][lrow] = b.w;
        __syncthreads();
#pragma unroll
        for (int k = 0; k < 16; ++k) {
            float4 ra = *(const float4*)&As[k][tm * 4];
            float4 rb = *(const float4*)&Bs[k][tn * 4];
            acc[0][0] += ra.x * rb.x; acc[0][1] += ra.x * rb.y; acc[0][2] += ra.x * rb.z; acc[0][3] += ra.x * rb.w;
            acc[1][0] += ra.y * rb.x; acc[1][1] += ra.y * rb.y; acc[1][2] += ra.y * rb.z; acc[1][3] += ra.y * rb.w;
            acc[2][0] += ra.z * rb.x; acc[2][1] += ra.z * rb.y; acc[2][2] += ra.z * rb.z; acc[2][3] += ra.z * rb.w;
            acc[3][0] += ra.w * rb.x; acc[3][1] += ra.w * rb.y; acc[3][2] += ra.w * rb.z; acc[3][3] += ra.w * rb.w;
        }
        __syncthreads();
    }
    float4 bv = *(const float4*)(bias + bn + tn * 4);
#pragma unroll
    for (int i = 0; i < 4; ++i) {
        int mi = bm + tm * 4 + i;
        float4 v;
        v.x = acc[i][0] + bv.x; v.y = acc[i][1] + bv.y;
        v.z = acc[i][2] + bv.z; v.w = acc[i][3] + bv.w;
        if (GELU) {
            v.x = 0.5f * v.x * (1.f + erff(v.x * 0.70710678118f));
            v.y = 0.5f * v.y * (1.f + erff(v.y * 0.70710678118f));
            v.z = 0.5f * v.z * (1.f + erff(v.z * 0.70710678118f));
            v.w = 0.5f * v.w * (1.f + erff(v.w * 0.70710678118f));
        }
        if (RES) {
            float4 r = *(const float4*)(res + (size_t)mi * Nn + bn + tn * 4);
            v.x += r.x; v.y += r.y; v.z += r.z; v.w += r.w;
        }
        *(float4*)(out + (size_t)mi * Nn + bn + tn * 4) = v;
    }
}

// ---------------- CPE conv GEMM: out[m,i] = sum_kk sum_j gather(feat)[m,kk*C+j] * W[kk,i,j] + b[i]
__global__ void cpe_gemm_kernel(const float* __restrict__ feat, const int* __restrict__ nbr,
                                const float* __restrict__ W, const float* __restrict__ bias,
                                float* __restrict__ out)
{
    __shared__ float As[16][68];
    __shared__ float Bs[16][68];
    const int bm = blockIdx.y * 64, bn = blockIdx.x * 64;
    const int t = threadIdx.x;
    const int lrow = t >> 2, lseg = t & 3;
    const int tm = t >> 4, tn = t & 15;
    float acc[4][4] = {};

    for (int kk = 0; kk < 27; ++kk) {
        const int nb = nbr[(size_t)(bm + lrow) * 27 + kk];
        const float* Wk = W + (size_t)kk * C * C + (size_t)(bn + lrow) * C + lseg * 4;
        for (int j0 = 0; j0 < C; j0 += 16) {
            float4 a = make_float4(0.f, 0.f, 0.f, 0.f);
            if (nb >= 0) a = *(const float4*)(feat + (size_t)nb * C + j0 + lseg * 4);
            float4 b = *(const float4*)(Wk + j0);
            As[lseg * 4 + 0][lrow] = a.x; As[lseg * 4 + 1][lrow] = a.y;
            As[lseg * 4 + 2][lrow] = a.z; As[lseg * 4 + 3][lrow] = a.w;
            Bs[lseg * 4 + 0][lrow] = b.x; Bs[lseg * 4 + 1][lrow] = b.y;
            Bs[lseg * 4 + 2][lrow] = b.z; Bs[lseg * 4 + 3][lrow] = b.w;
            __syncthreads();
#pragma unroll
            for (int k = 0; k < 16; ++k) {
                float4 ra = *(const float4*)&As[k][tm * 4];
                float4 rb = *(const float4*)&Bs[k][tn * 4];
                acc[0][0] += ra.x * rb.x; acc[0][1] += ra.x * rb.y; acc[0][2] += ra.x * rb.z; acc[0][3] += ra.x * rb.w;
                acc[1][0] += ra.y * rb.x; acc[1][1] += ra.y * rb.y; acc[1][2] += ra.y * rb.z; acc[1][3] += ra.y * rb.w;
                acc[2][0] += ra.z * rb.x; acc[2][1] += ra.z * rb.y; acc[2][2] += ra.z * rb.z; acc[2][3] += ra.z * rb.w;
                acc[3][0] += ra.w * rb.x; acc[3][1] += ra.w * rb.y; acc[3][2] += ra.w * rb.z; acc[3][3] += ra.w * rb.w;
            }
            __syncthreads();
        }
    }
    float4 bv = *(const float4*)(bias + bn + tn * 4);
#pragma unroll
    for (int i = 0; i < 4; ++i) {
        int mi = bm + tm * 4 + i;
        float4 v;
        v.x = acc[i][0] + bv.x; v.y = acc[i][1] + bv.y;
        v.z = acc[i][2] + bv.z; v.w = acc[i][3] + bv.w;
        *(float4*)(out + (size_t)mi * C + bn + tn * 4) = v;
    }
}

// ---------------- LayerNorm: out = (res +) LN(in)*g + b ----------------
__global__ void ln_kernel(const float* __restrict__ in, const float* __restrict__ res,
                          const float* __restrict__ gam, const float* __restrict__ bet,
                          float* __restrict__ out)
{
    const int n = blockIdx.x;
    const int t = threadIdx.x;   // 128, 4 floats each
    float4 v = *(const float4*)(in + (size_t)n * C + t * 4);
    float s1 = v.x + v.y + v.z + v.w;
    float s2 = v.x * v.x + v.y * v.y + v.z * v.z + v.w * v.w;
#pragma unroll
    for (int o = 16; o; o >>= 1) {
        s1 += __shfl_xor_sync(0xffffffffu, s1, o);
        s2 += __shfl_xor_sync(0xffffffffu, s2, o);
    }
    __shared__ float sh1[4], sh2[4];
    const int wid = t >> 5, lane = t & 31;
    if (lane == 0) { sh1[wid] = s1; sh2[wid] = s2; }
    __syncthreads();
    float S1 = sh1[0] + sh1[1] + sh1[2] + sh1[3];
    float S2 = sh2[0] + sh2[1] + sh2[2] + sh2[3];
    float mean = S1 * (1.f / C);
    float var = S2 * (1.f / C) - mean * mean;
    float inv = rsqrtf(var + 1e-5f);
    float4 g4 = *(const float4*)(gam + t * 4);
    float4 b4 = *(const float4*)(bet + t * 4);
    float4 o4;
    o4.x = (v.x - mean) * inv * g4.x + b4.x;
    o4.y = (v.y - mean) * inv * g4.y + b4.y;
    o4.z = (v.z - mean) * inv * g4.z + b4.z;
    o4.w = (v.w - mean) * inv * g4.w + b4.w;
    if (res != nullptr) {
        float4 r4 = *(const float4*)(res + (size_t)n * C + t * 4);
        o4.x += r4.x; o4.y += r4.y; o4.z += r4.z; o4.w += r4.w;
    }
    *(float4*)(out + (size_t)n * C + t * 4) = o4;
}

// ---------------- windowed attention (flash-style, fp32) ----------------
// block = (q-tile of 64, head, patch); 256 threads: row = t>>2 (64), grp = t&3
__global__ void attn_kernel(const float* __restrict__ qkv, const int* __restrict__ order,
                            float* __restrict__ o)
{
    const int qt = blockIdx.x;   // 0..15
    const int h  = blockIdx.y;   // 0..7
    const int p  = blockIdx.z;   // 0..15
    __shared__ float Qs[64][65];
    __shared__ float Ks[32][65];
    __shared__ float Vs[32][64];
    __shared__ float Ps[64][33];
    const int t = threadIdx.x;
    const int row = t >> 2, grp = t & 3;

    // load Q tile (scaled)
    for (int i = t; i < 64 * 16; i += 256) {
        int r = i >> 4, c4 = i & 15;
        int n = order[p * KWIN + qt * 64 + r];
        float4 v = *(const float4*)(qkv + (size_t)n * (3 * C) + h * HD + c4 * 4);
        Qs[r][c4 * 4 + 0] = v.x * SCALE; Qs[r][c4 * 4 + 1] = v.y * SCALE;
        Qs[r][c4 * 4 + 2] = v.z * SCALE; Qs[r][c4 * 4 + 3] = v.w * SCALE;
    }
    const int n_out = order[p * KWIN + qt * 64 + row];

    float m = -1e30f, l = 0.f;
    float oacc[16];
#pragma unroll
    for (int dd = 0; dd < 16; ++dd) oacc[dd] = 0.f;

    for (int kt = 0; kt < KWIN / 32; ++kt) {
        __syncthreads();
        for (int i = t; i < 32 * 16; i += 256) {
            int r = i >> 4, c4 = i & 15;
            int n = order[p * KWIN + kt * 32 + r];
            float4 kv = *(const float4*)(qkv + (size_t)n * (3 * C) + C + h * HD + c4 * 4);
            Ks[r][c4 * 4 + 0] = kv.x; Ks[r][c4 * 4 + 1] = kv.y;
            Ks[r][c4 * 4 + 2] = kv.z; Ks[r][c4 * 4 + 3] = kv.w;
            float4 vv = *(const float4*)(qkv + (size_t)n * (3 * C) + 2 * C + h * HD + c4 * 4);
            Vs[r][c4 * 4 + 0] = vv.x; Vs[r][c4 * 4 + 1] = vv.y;
            Vs[r][c4 * 4 + 2] = vv.z; Vs[r][c4 * 4 + 3] = vv.w;
        }
        __syncthreads();

        float s[8];
#pragma unroll
        for (int cc = 0; cc < 8; ++cc) {
            float acc = 0.f;
            const int c = grp * 8 + cc;
#pragma unroll
            for (int d = 0; d < 64; ++d) acc += Qs[row][d] * Ks[c][d];
            s[cc] = acc;
        }
        float mx = s[0];
#pragma unroll
        for (int cc = 1; cc < 8; ++cc) mx = fmaxf(mx, s[cc]);
        mx = fmaxf(mx, __shfl_xor_sync(0xffffffffu, mx, 1));
        mx = fmaxf(mx, __shfl_xor_sync(0xffffffffu, mx, 2));
        const float mnew = fmaxf(m, mx);
        const float alpha = __expf(m - mnew);
        float psum = 0.f;
#pragma unroll
        for (int cc = 0; cc < 8; ++cc) {
            float pv = __expf(s[cc] - mnew);
            psum += pv;
            Ps[row][grp * 8 + cc] = pv;
        }
        psum += __shfl_xor_sync(0xffffffffu, psum, 1);
        psum += __shfl_xor_sync(0xffffffffu, psum, 2);
        l = l * alpha + psum;
        m = mnew;
#pragma unroll
        for (int dd = 0; dd < 16; ++dd) oacc[dd] *= alpha;
        __syncwarp();
#pragma unroll
        for (int c = 0; c < 32; ++c) {
            float pv = Ps[row][c];
#pragma unroll
            for (int dd = 0; dd < 16; ++dd) oacc[dd] += pv * Vs[c][grp * 16 + dd];
        }
        __syncwarp();
    }
    const float inv = 1.f / l;
#pragma unroll
    for (int dd = 0; dd < 16; ++dd)
        o[(size_t)n_out * C + h * HD + grp * 16 + dd] = oacc[dd] * inv;
}

// ---------------- launch ----------------
extern "C" void kernel_launch(void* const* d_in, const int* in_sizes, int n_in,
                              void* d_out, int out_size)
{
    const float* feat      = (const float*)d_in[0];
    const int*   nbr       = (const int*)d_in[1];
    const int*   order     = (const int*)d_in[2];
    const float* cpe_w     = (const float*)d_in[3];
    const float* cpe_b     = (const float*)d_in[4];
    const float* cpe_lin_w = (const float*)d_in[5];
    const float* cpe_lin_b = (const float*)d_in[6];
    const float* cpe_ln_g  = (const float*)d_in[7];
    const float* cpe_ln_b  = (const float*)d_in[8];
    const float* ln1_g     = (const float*)d_in[9];
    const float* ln1_b     = (const float*)d_in[10];
    const float* qkv_w     = (const float*)d_in[11];
    const float* qkv_b     = (const float*)d_in[12];
    const float* proj_w    = (const float*)d_in[13];
    const float* proj_b    = (const float*)d_in[14];
    const float* ln2_g     = (const float*)d_in[15];
    const float* ln2_b     = (const float*)d_in[16];
    const float* fc1_w     = (const float*)d_in[17];
    const float* fc1_b     = (const float*)d_in[18];
    const float* fc2_w     = (const float*)d_in[19];
    const float* fc2_b     = (const float*)d_in[20];
    float* out = (float*)d_out;

    float *tmp1, *tmp2, *feat1, *x, *qkvb, *ob, *y;
    cudaGetSymbolAddress((void**)&tmp1,  g_tmp1);
    cudaGetSymbolAddress((void**)&tmp2,  g_tmp2);
    cudaGetSymbolAddress((void**)&feat1, g_feat1);
    cudaGetSymbolAddress((void**)&x,     g_x);
    cudaGetSymbolAddress((void**)&qkvb,  g_qkv);
    cudaGetSymbolAddress((void**)&ob,    g_o);
    cudaGetSymbolAddress((void**)&y,     g_y);

    const int MB = NPTS / 64;  // 256 row-tiles

    // 1) CPE 27-tap conv: tmp1 = conv(feat) + cpe_b
    cpe_gemm_kernel<<<dim3(C / 64, MB), 256>>>(feat, nbr, cpe_w, cpe_b, tmp1);
    // 2) tmp2 = tmp1 @ cpe_lin_w^T + b
    sgemm_kernel<false, false><<<dim3(C / 64, MB), 256>>>(tmp1, cpe_lin_w, cpe_lin_b, nullptr, tmp2, NPTS, C, C);
    // 3) feat1 = feat + LN(tmp2)
    ln_kernel<<<NPTS, 128>>>(tmp2, feat, cpe_ln_g, cpe_ln_b, feat1);
    // 4) x = LN(feat1)
    ln_kernel<<<NPTS, 128>>>(feat1, nullptr, ln1_g, ln1_b, x);
    // 5) qkv = x @ qkv_w^T + b
    sgemm_kernel<false, false><<<dim3(3 * C / 64, MB), 256>>>(x, qkv_w, qkv_b, nullptr, qkvb, NPTS, 3 * C, C);
    // 6) attention (gather by order, scatter back)
    attn_kernel<<<dim3(KWIN / 64, H, P), 256>>>(qkvb, order, ob);
    // 7) feat2 = feat1 + ob @ proj_w^T + b   -> tmp1
    sgemm_kernel<false, true><<<dim3(C / 64, MB), 256>>>(ob, proj_w, proj_b, feat1, tmp1, NPTS, C, C);
    // 8) x = LN(feat2)
    ln_kernel<<<NPTS, 128>>>(tmp1, nullptr, ln2_g, ln2_b, x);
    // 9) y = gelu(x @ fc1_w^T + b)
    sgemm_kernel<true, false><<<dim3(4 * C / 64, MB), 256>>>(x, fc1_w, fc1_b, nullptr, y, NPTS, 4 * C, C);
    // 10) out = feat2 + y @ fc2_w^T + b
    sgemm_kernel<false, true><<<dim3(C / 64, MB), 256>>>(y, fc2_w, fc2_b, tmp1, out, NPTS, C, 4 * C);
}

// round 3
// speedup vs baseline: 1.6303x; 1.6303x over previous
#include <cuda_runtime.h>
#include <cuda_bf16.h>
#include <math.h>
#include <stdint.h>

#define NPTS 16384
#define C 512
#define H 8
#define HD 64
#define KWIN 1024
#define P (NPTS / KWIN)
#define SCALE 0.125f

// ---------------- scratch ----------------
__device__ float g_tmp1[NPTS * C];
__device__ float g_tmp2[NPTS * C];
__device__ float g_feat1[NPTS * C];
__device__ float g_x[NPTS * C];
__device__ float g_qkv[NPTS * 3 * C];
__device__ float g_o[NPTS * C];
__device__ float g_y[NPTS * 4 * C];
// split-precision weight pool (hi/lo bf16)
#define WPOOL (27*C*C + C*C + 3*C*C + C*C + 4*C*C + 4*C*C)
__device__ __nv_bfloat16 g_whi[WPOOL];
__device__ __nv_bfloat16 g_wlo[WPOOL];

#define OFF_CPE   0
#define OFF_LIN   (27*C*C)
#define OFF_QKV   (OFF_LIN + C*C)
#define OFF_PROJ  (OFF_QKV + 3*C*C)
#define OFF_FC1   (OFF_PROJ + C*C)
#define OFF_FC2   (OFF_FC1 + 4*C*C)

// ---------------- helpers ----------------
__device__ __forceinline__ uint32_t s2u(const void* p) {
    return (uint32_t)__cvta_generic_to_shared(p);
}
__device__ __forceinline__ void ldmx4(uint32_t& r0, uint32_t& r1, uint32_t& r2, uint32_t& r3,
                                      uint32_t addr) {
    asm volatile("ldmatrix.sync.aligned.m8n8.x4.shared.b16 {%0,%1,%2,%3}, [%4];"
                 : "=r"(r0), "=r"(r1), "=r"(r2), "=r"(r3) : "r"(addr));
}
__device__ __forceinline__ void mma_bf16(float* d, const uint32_t* a, uint32_t b0, uint32_t b1) {
    asm volatile("mma.sync.aligned.m16n8k16.row.col.f32.bf16.bf16.f32 "
                 "{%0,%1,%2,%3},{%4,%5,%6,%7},{%8,%9},{%0,%1,%2,%3};"
                 : "+f"(d[0]), "+f"(d[1]), "+f"(d[2]), "+f"(d[3])
                 : "r"(a[0]), "r"(a[1]), "r"(a[2]), "r"(a[3]), "r"(b0), "r"(b1));
}
// swizzled smem index (halves). Row stride 32 halves (64B); 16B chunk xor'd by (r>>1)&3.
__device__ __forceinline__ int sidx(int r, int k) {
    return r * 32 + ((((k >> 3) ^ ((r >> 1) & 3)) << 3) | (k & 7));
}

// split 8 fp32 -> 8 bf16 hi + 8 bf16 lo
__device__ __forceinline__ void cvt8(float4 f0, float4 f1, uint4& hi, uint4& lo) {
    __nv_bfloat162 h, l;
    h = __floats2bfloat162_rn(f0.x, f0.y);
    l = __floats2bfloat162_rn(f0.x - __bfloat162float(h.x), f0.y - __bfloat162float(h.y));
    hi.x = *(uint32_t*)&h; lo.x = *(uint32_t*)&l;
    h = __floats2bfloat162_rn(f0.z, f0.w);
    l = __floats2bfloat162_rn(f0.z - __bfloat162float(h.x), f0.w - __bfloat162float(h.y));
    hi.y = *(uint32_t*)&h; lo.y = *(uint32_t*)&l;
    h = __floats2bfloat162_rn(f1.x, f1.y);
    l = __floats2bfloat162_rn(f1.x - __bfloat162float(h.x), f1.y - __bfloat162float(h.y));
    hi.z = *(uint32_t*)&h; lo.z = *(uint32_t*)&l;
    h = __floats2bfloat162_rn(f1.z, f1.w);
    l = __floats2bfloat162_rn(f1.z - __bfloat162float(h.x), f1.w - __bfloat162float(h.y));
    hi.w = *(uint32_t*)&h; lo.w = *(uint32_t*)&l;
}

// SMEM layout per stage (halves): Ahi 0, Alo 4096, Bhi 8192, Blo 12288. Stage stride 16384.
#define ST_STRIDE 16384
#define SM_AHI 0
#define SM_ALO 4096
#define SM_BHI 8192
#define SM_BLO 12288
#define SMEM_BYTES (2 * ST_STRIDE * 2)

// ---------------- weight split prepass ----------------
__global__ void w_prep(const float* __restrict__ src, __nv_bfloat16* __restrict__ hi,
                       __nv_bfloat16* __restrict__ lo, int n)
{
    int i = (blockIdx.x * blockDim.x + threadIdx.x) * 8;
    if (i >= n) return;
    float4 f0 = *(const float4*)(src + i);
    float4 f1 = *(const float4*)(src + i + 4);
    uint4 h, l;
    cvt8(f0, f1, h, l);
    *(uint4*)(hi + i) = h;
    *(uint4*)(lo + i) = l;
}

// ---------------- core compute on one resident chunk ----------------
__device__ __forceinline__ void mma_chunk(const __nv_bfloat16* sbuf, int wm, int wn, int lane,
                                          float acc[4][4][4])
{
#pragma unroll
    for (int kk16 = 0; kk16 < 2; ++kk16) {
        const int kc = kk16 * 2 + (lane >> 4);   // 16B chunk index for this lane
        uint32_t ah[4][4], al[4][4], bh[2][4], bl[2][4];
#pragma unroll
        for (int mf = 0; mf < 4; ++mf) {
            const int row = wm * 64 + mf * 16 + (lane & 15);
            const int off = sidx(row, kc * 8);
            ldmx4(ah[mf][0], ah[mf][1], ah[mf][2], ah[mf][3], s2u(sbuf + SM_AHI + off));
            ldmx4(al[mf][0], al[mf][1], al[mf][2], al[mf][3], s2u(sbuf + SM_ALO + off));
        }
#pragma unroll
        for (int np = 0; np < 2; ++np) {
            const int row = wn * 32 + np * 16 + (lane & 15);
            const int off = sidx(row, kc * 8);
            ldmx4(bh[np][0], bh[np][1], bh[np][2], bh[np][3], s2u(sbuf + SM_BHI + off));
            ldmx4(bl[np][0], bl[np][1], bl[np][2], bl[np][3], s2u(sbuf + SM_BLO + off));
        }
#pragma unroll
        for (int mf = 0; mf < 4; ++mf) {
#pragma unroll
            for (int nf = 0; nf < 4; ++nf) {
                const int pr = nf >> 1, sb = nf & 1;
                mma_bf16(acc[mf][nf], ah[mf], bh[pr][sb], bh[pr][sb + 2]);
                mma_bf16(acc[mf][nf], ah[mf], bl[pr][sb], bl[pr][sb + 2]);
                mma_bf16(acc[mf][nf], al[mf], bh[pr][sb], bh[pr][sb + 2]);
            }
        }
    }
}

// ---------------- epilogue ----------------
template <bool GELU, bool RES>
__device__ __forceinline__ void epilogue(float acc[4][4][4], int bm, int bn, int Nn,
                                         int wm, int wn, int lane,
                                         const float* bias, const float* res, float* out)
{
#pragma unroll
    for (int mf = 0; mf < 4; ++mf) {
#pragma unroll
        for (int nf = 0; nf < 4; ++nf) {
            const int n0 = bn + wn * 32 + nf * 8 + 2 * (lane & 3);
            const float b0 = __ldg(bias + n0), b1 = __ldg(bias + n0 + 1);
#pragma unroll
            for (int half = 0; half < 2; ++half) {
                const int m = bm + wm * 64 + mf * 16 + (lane >> 2) + half * 8;
                float v0 = acc[mf][nf][half * 2 + 0] + b0;
                float v1 = acc[mf][nf][half * 2 + 1] + b1;
                if (GELU) {
                    v0 = 0.5f * v0 * (1.f + erff(v0 * 0.70710678118f));
                    v1 = 0.5f * v1 * (1.f + erff(v1 * 0.70710678118f));
                }
                if (RES) {
                    float2 r2 = *(const float2*)(res + (size_t)m * Nn + n0);
                    v0 += r2.x; v1 += r2.y;
                }
                *(float2*)(out + (size_t)m * Nn + n0) = make_float2(v0, v1);
            }
        }
    }
}

// ---------------- generic GEMM: out = act(A @ B^T + bias) (+res) ----------------
// A fp32 [M,Kk]; B pre-split bf16 hi/lo [Nn,Kk]
template <bool GELU, bool RES>
__global__ void __launch_bounds__(256)
tc_gemm(const float* __restrict__ A,
        const __nv_bfloat16* __restrict__ Bhi, const __nv_bfloat16* __restrict__ Blo,
        const float* __restrict__ bias, const float* __restrict__ res,
        float* __restrict__ out, int Nn, int Kk)
{
    extern __shared__ __align__(16) __nv_bfloat16 smem[];
    const int t = threadIdx.x, lane = t & 31, warp = t >> 5;
    const int wm = warp >> 2, wn = warp & 3;
    const int bm = blockIdx.y * 128, bn = blockIdx.x * 128;

    float acc[4][4][4];
#pragma unroll
    for (int a = 0; a < 4; ++a)
#pragma unroll
        for (int b = 0; b < 4; ++b)
#pragma unroll
            for (int c = 0; c < 4; ++c) acc[a][b][c] = 0.f;

    const int nchunk = Kk / 32;
    const int r0 = t >> 2, c0 = t & 3;            // slot 0
    const int r1 = (t + 256) >> 2, c1 = t & 3;    // slot 1

    // preload chunk 0
    {
        const float* ap0 = A + (size_t)(bm + r0) * Kk + c0 * 8;
        const float* ap1 = A + (size_t)(bm + r1) * Kk + c1 * 8;
        float4 a00 = *(const float4*)ap0, a01 = *(const float4*)(ap0 + 4);
        float4 a10 = *(const float4*)ap1, a11 = *(const float4*)(ap1 + 4);
        uint4 h, l;
        cvt8(a00, a01, h, l);
        *(uint4*)(smem + SM_AHI + sidx(r0, c0 * 8)) = h;
        *(uint4*)(smem + SM_ALO + sidx(r0, c0 * 8)) = l;
        cvt8(a10, a11, h, l);
        *(uint4*)(smem + SM_AHI + sidx(r1, c1 * 8)) = h;
        *(uint4*)(smem + SM_ALO + sidx(r1, c1 * 8)) = l;
        *(uint4*)(smem + SM_BHI + sidx(r0, c0 * 8)) = *(const uint4*)(Bhi + (size_t)(bn + r0) * Kk + c0 * 8);
        *(uint4*)(smem + SM_BLO + sidx(r0, c0 * 8)) = *(const uint4*)(Blo + (size_t)(bn + r0) * Kk + c0 * 8);
        *(uint4*)(smem + SM_BHI + sidx(r1, c1 * 8)) = *(const uint4*)(Bhi + (size_t)(bn + r1) * Kk + c1 * 8);
        *(uint4*)(smem + SM_BLO + sidx(r1, c1 * 8)) = *(const uint4*)(Blo + (size_t)(bn + r1) * Kk + c1 * 8);
    }
    __syncthreads();

    for (int chunk = 0; chunk < nchunk; ++chunk) {
        const __nv_bfloat16* cur = smem + (chunk & 1) * ST_STRIDE;
        __nv_bfloat16* nxt = smem + ((chunk + 1) & 1) * ST_STRIDE;
        float4 pa[2][2]; uint4 pbh[2], pbl[2];
        const bool more = (chunk + 1 < nchunk);
        if (more) {
            const int kb = (chunk + 1) * 32;
            const float* ap0 = A + (size_t)(bm + r0) * Kk + kb + c0 * 8;
            const float* ap1 = A + (size_t)(bm + r1) * Kk + kb + c1 * 8;
            pa[0][0] = *(const float4*)ap0; pa[0][1] = *(const float4*)(ap0 + 4);
            pa[1][0] = *(const float4*)ap1; pa[1][1] = *(const float4*)(ap1 + 4);
            pbh[0] = *(const uint4*)(Bhi + (size_t)(bn + r0) * Kk + kb + c0 * 8);
            pbl[0] = *(const uint4*)(Blo + (size_t)(bn + r0) * Kk + kb + c0 * 8);
            pbh[1] = *(const uint4*)(Bhi + (size_t)(bn + r1) * Kk + kb + c1 * 8);
            pbl[1] = *(const uint4*)(Blo + (size_t)(bn + r1) * Kk + kb + c1 * 8);
        }
        mma_chunk(cur, wm, wn, lane, acc);
        __syncthreads();
        if (more) {
            uint4 h, l;
            cvt8(pa[0][0], pa[0][1], h, l);
            *(uint4*)(nxt + SM_AHI + sidx(r0, c0 * 8)) = h;
            *(uint4*)(nxt + SM_ALO + sidx(r0, c0 * 8)) = l;
            cvt8(pa[1][0], pa[1][1], h, l);
            *(uint4*)(nxt + SM_AHI + sidx(r1, c1 * 8)) = h;
            *(uint4*)(nxt + SM_ALO + sidx(r1, c1 * 8)) = l;
            *(uint4*)(nxt + SM_BHI + sidx(r0, c0 * 8)) = pbh[0];
            *(uint4*)(nxt + SM_BLO + sidx(r0, c0 * 8)) = pbl[0];
            *(uint4*)(nxt + SM_BHI + sidx(r1, c1 * 8)) = pbh[1];
            *(uint4*)(nxt + SM_BLO + sidx(r1, c1 * 8)) = pbl[1];
        }
        __syncthreads();
    }
    epilogue<GELU, RES>(acc, bm, bn, Nn, wm, wn, lane, bias, res, out);
}

// ---------------- CPE conv: 27-tap gathered GEMM ----------------
__global__ void __launch_bounds__(256)
tc_cpe(const float* __restrict__ feat, const int* __restrict__ nbr,
       const __nv_bfloat16* __restrict__ Whi, const __nv_bfloat16* __restrict__ Wlo,
       const float* __restrict__ bias, float* __restrict__ out)
{
    extern __shared__ __align__(16) __nv_bfloat16 smem[];
    const int t = threadIdx.x, lane = t & 31, warp = t >> 5;
    const int wm = warp >> 2, wn = warp & 3;
    const int bm = blockIdx.y * 128, bn = blockIdx.x * 128;

    float acc[4][4][4];
#pragma unroll
    for (int a = 0; a < 4; ++a)
#pragma unroll
        for (int b = 0; b < 4; ++b)
#pragma unroll
            for (int c = 0; c < 4; ++c) acc[a][b][c] = 0.f;

    const int nchunk = 27 * (C / 32);
    const int r0 = t >> 2, c0 = t & 3;
    const int r1 = (t + 256) >> 2, c1 = t & 3;

    // preload chunk 0 (kk=0, kb=0)
    {
        const int nb0 = __ldg(nbr + (size_t)(bm + r0) * 27);
        const int nb1 = __ldg(nbr + (size_t)(bm + r1) * 27);
        float4 a00 = make_float4(0,0,0,0), a01 = a00, a10 = a00, a11 = a00;
        if (nb0 >= 0) {
            const float* ap = feat + (size_t)nb0 * C + c0 * 8;
            a00 = *(const float4*)ap; a01 = *(const float4*)(ap + 4);
        }
        if (nb1 >= 0) {
            const float* ap = feat + (size_t)nb1 * C + c1 * 8;
            a10 = *(const float4*)ap; a11 = *(const float4*)(ap + 4);
        }
        uint4 h, l;
        cvt8(a00, a01, h, l);
        *(uint4*)(smem + SM_AHI + sidx(r0, c0 * 8)) = h;
        *(uint4*)(smem + SM_ALO + sidx(r0, c0 * 8)) = l;
        cvt8(a10, a11, h, l);
        *(uint4*)(smem + SM_AHI + sidx(r1, c1 * 8)) = h;
        *(uint4*)(smem + SM_ALO + sidx(r1, c1 * 8)) = l;
        *(uint4*)(smem + SM_BHI + sidx(r0, c0 * 8)) = *(const uint4*)(Whi + (size_t)(bn + r0) * C + c0 * 8);
        *(uint4*)(smem + SM_BLO + sidx(r0, c0 * 8)) = *(const uint4*)(Wlo + (size_t)(bn + r0) * C + c0 * 8);
        *(uint4*)(smem + SM_BHI + sidx(r1, c1 * 8)) = *(const uint4*)(Whi + (size_t)(bn + r1) * C + c1 * 8);
        *(uint4*)(smem + SM_BLO + sidx(r1, c1 * 8)) = *(const uint4*)(Wlo + (size_t)(bn + r1) * C + c1 * 8);
    }
    __syncthreads();

    for (int chunk = 0; chunk < nchunk; ++chunk) {
        const __nv_bfloat16* cur = smem + (chunk & 1) * ST_STRIDE;
        __nv_bfloat16* nxt = smem + ((chunk + 1) & 1) * ST_STRIDE;
        float4 pa[2][2]; uint4 pbh[2], pbl[2];
        const bool more = (chunk + 1 < nchunk);
        if (more) {
            const int nc = chunk + 1;
            const int kk = nc >> 4, kb = (nc & 15) * 32;
            const int nb0 = __ldg(nbr + (size_t)(bm + r0) * 27 + kk);
            const int nb1 = __ldg(nbr + (size_t)(bm + r1) * 27 + kk);
            pa[0][0] = make_float4(0,0,0,0); pa[0][1] = pa[0][0];
            pa[1][0] = pa[0][0]; pa[1][1] = pa[0][0];
            if (nb0 >= 0) {
                const float* ap = feat + (size_t)nb0 * C + kb + c0 * 8;
                pa[0][0] = *(const float4*)ap; pa[0][1] = *(const float4*)(ap + 4);
            }
            if (nb1 >= 0) {
                const float* ap = feat + (size_t)nb1 * C + kb + c1 * 8;
                pa[1][0] = *(const float4*)ap; pa[1][1] = *(const float4*)(ap + 4);
            }
            const size_t wb = (size_t)kk * C * C;
            pbh[0] = *(const uint4*)(Whi + wb + (size_t)(bn + r0) * C + kb + c0 * 8);
            pbl[0] = *(const uint4*)(Wlo + wb + (size_t)(bn + r0) * C + kb + c0 * 8);
            pbh[1] = *(const uint4*)(Whi + wb + (size_t)(bn + r1) * C + kb + c1 * 8);
            pbl[1] = *(const uint4*)(Wlo + wb + (size_t)(bn + r1) * C + kb + c1 * 8);
        }
        mma_chunk(cur, wm, wn, lane, acc);
        __syncthreads();
        if (more) {
            uint4 h, l;
            cvt8(pa[0][0], pa[0][1], h, l);
            *(uint4*)(nxt + SM_AHI + sidx(r0, c0 * 8)) = h;
            *(uint4*)(nxt + SM_ALO + sidx(r0, c0 * 8)) = l;
            cvt8(pa[1][0], pa[1][1], h, l);
            *(uint4*)(nxt + SM_AHI + sidx(r1, c1 * 8)) = h;
            *(uint4*)(nxt + SM_ALO + sidx(r1, c1 * 8)) = l;
            *(uint4*)(nxt + SM_BHI + sidx(r0, c0 * 8)) = pbh[0];
            *(uint4*)(nxt + SM_BLO + sidx(r0, c0 * 8)) = pbl[0];
            *(uint4*)(nxt + SM_BHI + sidx(r1, c1 * 8)) = pbh[1];
            *(uint4*)(nxt + SM_BLO + sidx(r1, c1 * 8)) = pbl[1];
        }
        __syncthreads();
    }
    epilogue<false, false>(acc, bm, bn, C, wm, wn, lane, bias, nullptr, out);
}

// ---------------- LayerNorm ----------------
__global__ void ln_kernel(const float* __restrict__ in, const float* __restrict__ res,
                          const float* __restrict__ gam, const float* __restrict__ bet,
                          float* __restrict__ out)
{
    const int n = blockIdx.x;
    const int t = threadIdx.x;
    float4 v = *(const float4*)(in + (size_t)n * C + t * 4);
    float s1 = v.x + v.y + v.z + v.w;
    float s2 = v.x * v.x + v.y * v.y + v.z * v.z + v.w * v.w;
#pragma unroll
    for (int o = 16; o; o >>= 1) {
        s1 += __shfl_xor_sync(0xffffffffu, s1, o);
        s2 += __shfl_xor_sync(0xffffffffu, s2, o);
    }
    __shared__ float sh1[4], sh2[4];
    const int wid = t >> 5, lane = t & 31;
    if (lane == 0) { sh1[wid] = s1; sh2[wid] = s2; }
    __syncthreads();
    float S1 = sh1[0] + sh1[1] + sh1[2] + sh1[3];
    float S2 = sh2[0] + sh2[1] + sh2[2] + sh2[3];
    float mean = S1 * (1.f / C);
    float var = S2 * (1.f / C) - mean * mean;
    float inv = rsqrtf(var + 1e-5f);
    float4 g4 = *(const float4*)(gam + t * 4);
    float4 b4 = *(const float4*)(bet + t * 4);
    float4 o4;
    o4.x = (v.x - mean) * inv * g4.x + b4.x;
    o4.y = (v.y - mean) * inv * g4.y + b4.y;
    o4.z = (v.z - mean) * inv * g4.z + b4.z;
    o4.w = (v.w - mean) * inv * g4.w + b4.w;
    if (res != nullptr) {
        float4 r4 = *(const float4*)(res + (size_t)n * C + t * 4);
        o4.x += r4.x; o4.y += r4.y; o4.z += r4.z; o4.w += r4.w;
    }
    *(float4*)(out + (size_t)n * C + t * 4) = o4;
}

// ---------------- attention (flash-style, fp32) ----------------
__global__ void attn_kernel(const float* __restrict__ qkv, const int* __restrict__ order,
                            float* __restrict__ o)
{
    const int qt = blockIdx.x;
    const int h  = blockIdx.y;
    const int p  = blockIdx.z;
    __shared__ float Qs[64][65];
    __shared__ float Ks[32][65];
    __shared__ float Vs[32][64];
    __shared__ float Ps[64][33];
    const int t = threadIdx.x;
    const int row = t >> 2, grp = t & 3;

    for (int i = t; i < 64 * 16; i += 256) {
        int r = i >> 4, c4 = i & 15;
        int n = order[p * KWIN + qt * 64 + r];
        float4 v = *(const float4*)(qkv + (size_t)n * (3 * C) + h * HD + c4 * 4);
        Qs[r][c4 * 4 + 0] = v.x * SCALE; Qs[r][c4 * 4 + 1] = v.y * SCALE;
        Qs[r][c4 * 4 + 2] = v.z * SCALE; Qs[r][c4 * 4 + 3] = v.w * SCALE;
    }
    const int n_out = order[p * KWIN + qt * 64 + row];

    float m = -1e30f, l = 0.f;
    float oacc[16];
#pragma unroll
    for (int dd = 0; dd < 16; ++dd) oacc[dd] = 0.f;

    for (int kt = 0; kt < KWIN / 32; ++kt) {
        __syncthreads();
        for (int i = t; i < 32 * 16; i += 256) {
            int r = i >> 4, c4 = i & 15;
            int n = order[p * KWIN + kt * 32 + r];
            float4 kv = *(const float4*)(qkv + (size_t)n * (3 * C) + C + h * HD + c4 * 4);
            Ks[r][c4 * 4 + 0] = kv.x; Ks[r][c4 * 4 + 1] = kv.y;
            Ks[r][c4 * 4 + 2] = kv.z; Ks[r][c4 * 4 + 3] = kv.w;
            float4 vv = *(const float4*)(qkv + (size_t)n * (3 * C) + 2 * C + h * HD + c4 * 4);
            Vs[r][c4 * 4 + 0] = vv.x; Vs[r][c4 * 4 + 1] = vv.y;
            Vs[r][c4 * 4 + 2] = vv.z; Vs[r][c4 * 4 + 3] = vv.w;
        }
        __syncthreads();

        float s[8];
#pragma unroll
        for (int cc = 0; cc < 8; ++cc) {
            float acc = 0.f;
            const int c = grp * 8 + cc;
#pragma unroll
            for (int d = 0; d < 64; ++d) acc += Qs[row][d] * Ks[c][d];
            s[cc] = acc;
        }
        float mx = s[0];
#pragma unroll
        for (int cc = 1; cc < 8; ++cc) mx = fmaxf(mx, s[cc]);
        mx = fmaxf(mx, __shfl_xor_sync(0xffffffffu, mx, 1));
        mx = fmaxf(mx, __shfl_xor_sync(0xffffffffu, mx, 2));
        const float mnew = fmaxf(m, mx);
        const float alpha = __expf(m - mnew);
        float psum = 0.f;
#pragma unroll
        for (int cc = 0; cc < 8; ++cc) {
            float pv = __expf(s[cc] - mnew);
            psum += pv;
            Ps[row][grp * 8 + cc] = pv;
        }
        psum += __shfl_xor_sync(0xffffffffu, psum, 1);
        psum += __shfl_xor_sync(0xffffffffu, psum, 2);
        l = l * alpha + psum;
        m = mnew;
#pragma unroll
        for (int dd = 0; dd < 16; ++dd) oacc[dd] *= alpha;
        __syncwarp();
#pragma unroll
        for (int c = 0; c < 32; ++c) {
            float pv = Ps[row][c];
#pragma unroll
            for (int dd = 0; dd < 16; ++dd) oacc[dd] += pv * Vs[c][grp * 16 + dd];
        }
        __syncwarp();
    }
    const float inv = 1.f / l;
#pragma unroll
    for (int dd = 0; dd < 16; ++dd)
        o[(size_t)n_out * C + h * HD + grp * 16 + dd] = oacc[dd] * inv;
}

// ---------------- launch ----------------
extern "C" void kernel_launch(void* const* d_in, const int* in_sizes, int n_in,
                              void* d_out, int out_size)
{
    const float* feat      = (const float*)d_in[0];
    const int*   nbr       = (const int*)d_in[1];
    const int*   order     = (const int*)d_in[2];
    const float* cpe_w     = (const float*)d_in[3];
    const float* cpe_b     = (const float*)d_in[4];
    const float* cpe_lin_w = (const float*)d_in[5];
    const float* cpe_lin_b = (const float*)d_in[6];
    const float* cpe_ln_g  = (const float*)d_in[7];
    const float* cpe_ln_b  = (const float*)d_in[8];
    const float* ln1_g     = (const float*)d_in[9];
    const float* ln1_b     = (const float*)d_in[10];
    const float* qkv_w     = (const float*)d_in[11];
    const float* qkv_b     = (const float*)d_in[12];
    const float* proj_w    = (const float*)d_in[13];
    const float* proj_b    = (const float*)d_in[14];
    const float* ln2_g     = (const float*)d_in[15];
    const float* ln2_b     = (const float*)d_in[16];
    const float* fc1_w     = (const float*)d_in[17];
    const float* fc1_b     = (const float*)d_in[18];
    const float* fc2_w     = (const float*)d_in[19];
    const float* fc2_b     = (const float*)d_in[20];
    float* out = (float*)d_out;

    float *tmp1, *tmp2, *feat1, *x, *qkvb, *ob, *y;
    __nv_bfloat16 *whi, *wlo;
    cudaGetSymbolAddress((void**)&tmp1,  g_tmp1);
    cudaGetSymbolAddress((void**)&tmp2,  g_tmp2);
    cudaGetSymbolAddress((void**)&feat1, g_feat1);
    cudaGetSymbolAddress((void**)&x,     g_x);
    cudaGetSymbolAddress((void**)&qkvb,  g_qkv);
    cudaGetSymbolAddress((void**)&ob,    g_o);
    cudaGetSymbolAddress((void**)&y,     g_y);
    cudaGetSymbolAddress((void**)&whi,   g_whi);
    cudaGetSymbolAddress((void**)&wlo,   g_wlo);

    cudaFuncSetAttribute(tc_gemm<false,false>, cudaFuncAttributeMaxDynamicSharedMemorySize, SMEM_BYTES);
    cudaFuncSetAttribute(tc_gemm<false,true>,  cudaFuncAttributeMaxDynamicSharedMemorySize, SMEM_BYTES);
    cudaFuncSetAttribute(tc_gemm<true,false>,  cudaFuncAttributeMaxDynamicSharedMemorySize, SMEM_BYTES);
    cudaFuncSetAttribute(tc_cpe,               cudaFuncAttributeMaxDynamicSharedMemorySize, SMEM_BYTES);

    // ---- weight split prepass ----
    {
        struct { const float* s; int off; int n; } ws[6] = {
            { cpe_w,     OFF_CPE,  27*C*C },
            { cpe_lin_w, OFF_LIN,  C*C },
            { qkv_w,     OFF_QKV,  3*C*C },
            { proj_w,    OFF_PROJ, C*C },
            { fc1_w,     OFF_FC1,  4*C*C },
            { fc2_w,     OFF_FC2,  4*C*C },
        };
        for (int i = 0; i < 6; ++i)
            w_prep<<<(ws[i].n / 8 + 255) / 256, 256>>>(ws[i].s, whi + ws[i].off, wlo + ws[i].off, ws[i].n);
    }

    const int MB = NPTS / 128;  // 128
    // 1) CPE 27-tap conv
    tc_cpe<<<dim3(C/128, MB), 256, SMEM_BYTES>>>(feat, nbr, whi + OFF_CPE, wlo + OFF_CPE, cpe_b, tmp1);
    // 2) cpe_lin
    tc_gemm<false,false><<<dim3(C/128, MB), 256, SMEM_BYTES>>>(tmp1, whi + OFF_LIN, wlo + OFF_LIN, cpe_lin_b, nullptr, tmp2, C, C);
    // 3) feat1 = feat + LN(tmp2)
    ln_kernel<<<NPTS, 128>>>(tmp2, feat, cpe_ln_g, cpe_ln_b, feat1);
    // 4) x = LN(feat1)
    ln_kernel<<<NPTS, 128>>>(feat1, nullptr, ln1_g, ln1_b, x);
    // 5) qkv
    tc_gemm<false,false><<<dim3(3*C/128, MB), 256, SMEM_BYTES>>>(x, whi + OFF_QKV, wlo + OFF_QKV, qkv_b, nullptr, qkvb, 3*C, C);
    // 6) attention
    attn_kernel<<<dim3(KWIN/64, H, P), 256>>>(qkvb, order, ob);
    // 7) feat2 = feat1 + proj(ob) -> tmp1
    tc_gemm<false,true><<<dim3(C/128, MB), 256, SMEM_BYTES>>>(ob, whi + OFF_PROJ, wlo + OFF_PROJ, proj_b, feat1, tmp1, C, C);
    // 8) x = LN(feat2)
    ln_kernel<<<NPTS, 128>>>(tmp1, nullptr, ln2_g, ln2_b, x);
    // 9) y = gelu(fc1(x))
    tc_gemm<true,false><<<dim3(4*C/128, MB), 256, SMEM_BYTES>>>(x, whi + OFF_FC1, wlo + OFF_FC1, fc1_b, nullptr, y, 4*C, C);
    // 10) out = feat2 + fc2(y)
    tc_gemm<false,true><<<dim3(C/128, MB), 256, SMEM_BYTES>>>(y, whi + OFF_FC2, wlo + OFF_FC2, fc2_b, tmp1, out, C, 4*C);
}

// round 4
// speedup vs baseline: 7.5976x; 4.6602x over previous
#include <cuda_runtime.h>
#include <cuda_fp16.h>
#include <math.h>
#include <stdint.h>

#define NPTS 16384
#define C 512
#define H 8
#define HD 64
#define KWIN 1024
#define P (NPTS / KWIN)
#define SCALE 0.125f
#define MAX_TILES 3328   // 26 taps * 128 tiles worst case

// ---------------- scratch ----------------
__device__ float g_tmp1[NPTS * C];
__device__ float g_tmp2[NPTS * C];
__device__ float g_feat1[NPTS * C];
__device__ float g_x[NPTS * C];
__device__ float g_qkv[NPTS * 3 * C];
__device__ float g_o[NPTS * C];
__device__ float g_y[NPTS * 4 * C];

#define WPOOL (27*C*C + C*C + 3*C*C + C*C + 4*C*C + 4*C*C)
__device__ __half g_wh[WPOOL];

#define OFF_CPE   0
#define OFF_LIN   (27*C*C)
#define OFF_QKV   (OFF_LIN + C*C)
#define OFF_PROJ  (OFF_QKV + 3*C*C)
#define OFF_FC1   (OFF_PROJ + C*C)
#define OFF_FC2   (OFF_FC1 + 4*C*C)

// sparse CPE bookkeeping
__device__ int g_cnt[26];
__device__ int g_cursor[26];
__device__ int g_pofs[27];
__device__ int g_ntiles;
__device__ int g_tiletap[MAX_TILES];
__device__ int2 g_plist[MAX_TILES * 128];

// ---------------- helpers ----------------
__device__ __forceinline__ uint32_t s2u(const void* p) {
    return (uint32_t)__cvta_generic_to_shared(p);
}
__device__ __forceinline__ void ldmx4(uint32_t& r0, uint32_t& r1, uint32_t& r2, uint32_t& r3,
                                      uint32_t addr) {
    asm volatile("ldmatrix.sync.aligned.m8n8.x4.shared.b16 {%0,%1,%2,%3}, [%4];"
                 : "=r"(r0), "=r"(r1), "=r"(r2), "=r"(r3) : "r"(addr));
}
__device__ __forceinline__ void ldmx4t(uint32_t& r0, uint32_t& r1, uint32_t& r2, uint32_t& r3,
                                       uint32_t addr) {
    asm volatile("ldmatrix.sync.aligned.m8n8.x4.trans.shared.b16 {%0,%1,%2,%3}, [%4];"
                 : "=r"(r0), "=r"(r1), "=r"(r2), "=r"(r3) : "r"(addr));
}
__device__ __forceinline__ void mma_f16(float* d, const uint32_t* a, uint32_t b0, uint32_t b1) {
    asm volatile("mma.sync.aligned.m16n8k16.row.col.f32.f16.f16.f32 "
                 "{%0,%1,%2,%3},{%4,%5,%6,%7},{%8,%9},{%0,%1,%2,%3};"
                 : "+f"(d[0]), "+f"(d[1]), "+f"(d[2]), "+f"(d[3])
                 : "r"(a[0]), "r"(a[1]), "r"(a[2]), "r"(a[3]), "r"(b0), "r"(b1));
}
// swizzled smem index for [128][32]-half tiles (row stride 64B)
__device__ __forceinline__ int sidx(int r, int k) {
    return r * 32 + ((((k >> 3) ^ ((r >> 1) & 3)) << 3) | (k & 7));
}
// swizzled smem index for [128][64]-half tiles (row stride 128B)
__device__ __forceinline__ int aidx(int r, int k) {
    return r * 64 + ((((k >> 3) ^ (r & 7)) << 3) | (k & 7));
}
__device__ __forceinline__ uint32_t h2u(__half2 h) { return *(uint32_t*)&h; }
__device__ __forceinline__ uint4 cvt8s(float4 f0, float4 f1) {
    __half2 a = __floats2half2_rn(f0.x, f0.y), b = __floats2half2_rn(f0.z, f0.w);
    __half2 c = __floats2half2_rn(f1.x, f1.y), d = __floats2half2_rn(f1.z, f1.w);
    return make_uint4(h2u(a), h2u(b), h2u(c), h2u(d));
}
__device__ __forceinline__ void cvt8h(float4 f0, float4 f1, uint4& hi, uint4& lo) {
    __half2 h, l;
    h = __floats2half2_rn(f0.x, f0.y);
    l = __floats2half2_rn(f0.x - __half2float(__low2half(h)), f0.y - __half2float(__high2half(h)));
    hi.x = h2u(h); lo.x = h2u(l);
    h = __floats2half2_rn(f0.z, f0.w);
    l = __floats2half2_rn(f0.z - __half2float(__low2half(h)), f0.w - __half2float(__high2half(h)));
    hi.y = h2u(h); lo.y = h2u(l);
    h = __floats2half2_rn(f1.x, f1.y);
    l = __floats2half2_rn(f1.x - __half2float(__low2half(h)), f1.y - __half2float(__high2half(h)));
    hi.z = h2u(h); lo.z = h2u(l);
    h = __floats2half2_rn(f1.z, f1.w);
    l = __floats2half2_rn(f1.z - __half2float(__low2half(h)), f1.w - __half2float(__high2half(h)));
    hi.w = h2u(h); lo.w = h2u(l);
}

// GEMM smem: stage = Ahi(4096) + Alo(4096) + B(4096) halves
#define ST_STRIDE 12288
#define SM_AHI 0
#define SM_ALO 4096
#define SM_B   8192
#define SMEM_BYTES (2 * ST_STRIDE * 2)

// ---------------- weight fp16 prepass ----------------
__global__ void w_prep(const float* __restrict__ src, __half* __restrict__ dst, int n)
{
    int i = (blockIdx.x * blockDim.x + threadIdx.x) * 8;
    if (i >= n) return;
    float4 f0 = *(const float4*)(src + i);
    float4 f1 = *(const float4*)(src + i + 4);
    *(uint4*)(dst + i) = cvt8s(f0, f1);
}

// ---------------- sparse CPE prepass ----------------
__global__ void prep_zero()
{
    int i = blockIdx.x * blockDim.x + threadIdx.x;
    if (i < 26) { g_cnt[i] = 0; g_cursor[i] = 0; }
    const int total = MAX_TILES * 128;
    for (int k = i; k < total; k += gridDim.x * blockDim.x)
        g_plist[k] = make_int2(-1, -1);
}
__global__ void prep_count(const int* __restrict__ nbr)
{
    int s = blockIdx.y, kk = (s < 13) ? s : s + 1;
    int n = blockIdx.x * blockDim.x + threadIdx.x;
    bool v = __ldg(nbr + (size_t)n * 27 + kk) >= 0;
    unsigned m = __ballot_sync(0xffffffffu, v);
    if ((threadIdx.x & 31) == 0 && m) atomicAdd(&g_cnt[s], __popc(m));
}
__global__ void prep_scan()
{
    __shared__ int sofs[27];
    if (threadIdx.x == 0) {
        int o = 0;
        for (int s = 0; s < 26; ++s) {
            sofs[s] = o; g_pofs[s] = o;
            o += ((g_cnt[s] + 127) >> 7) << 7;
        }
        sofs[26] = o; g_pofs[26] = o; g_ntiles = o >> 7;
    }
    __syncthreads();
    int nt = sofs[26] >> 7;
    for (int tile = threadIdx.x; tile < nt; tile += blockDim.x) {
        int pos = tile << 7;
        int s = 0;
        while (!(pos >= sofs[s] && pos < sofs[s + 1])) ++s;
        g_tiletap[tile] = (s < 13) ? s : s + 1;
    }
}
__global__ void prep_fill(const int* __restrict__ nbr)
{
    int s = blockIdx.y, kk = (s < 13) ? s : s + 1;
    int n = blockIdx.x * blockDim.x + threadIdx.x;
    int j = __ldg(nbr + (size_t)n * 27 + kk);
    bool v = j >= 0;
    unsigned m = __ballot_sync(0xffffffffu, v);
    int base = 0;
    if ((threadIdx.x & 31) == 0 && m) base = atomicAdd(&g_cursor[s], __popc(m));
    base = __shfl_sync(0xffffffffu, base, 0);
    if (v) {
        int pos = base + __popc(m & ((1u << (threadIdx.x & 31)) - 1));
        g_plist[g_pofs[s] + pos] = make_int2(n, j);
    }
}

// ---------------- core mma on one resident chunk ----------------
__device__ __forceinline__ void mma_chunk(const __half* sbuf, int wm, int wn, int lane,
                                          float acc[4][4][4])
{
#pragma unroll
    for (int kk16 = 0; kk16 < 2; ++kk16) {
        const int kc = kk16 * 2 + (lane >> 4);
        uint32_t ah[4][4], al[4][4], bb[2][4];
#pragma unroll
        for (int mf = 0; mf < 4; ++mf) {
            const int row = wm * 64 + mf * 16 + (lane & 15);
            const int off = sidx(row, kc * 8);
            ldmx4(ah[mf][0], ah[mf][1], ah[mf][2], ah[mf][3], s2u(sbuf + SM_AHI + off));
            ldmx4(al[mf][0], al[mf][1], al[mf][2], al[mf][3], s2u(sbuf + SM_ALO + off));
        }
#pragma unroll
        for (int np = 0; np < 2; ++np) {
            const int row = wn * 32 + np * 16 + (lane & 15);
            const int off = sidx(row, kc * 8);
            ldmx4(bb[np][0], bb[np][1], bb[np][2], bb[np][3], s2u(sbuf + SM_B + off));
        }
#pragma unroll
        for (int mf = 0; mf < 4; ++mf) {
#pragma unroll
            for (int nf = 0; nf < 4; ++nf) {
                const int pr = nf >> 1, sb = nf & 1;
                mma_f16(acc[mf][nf], ah[mf], bb[pr][sb], bb[pr][sb + 2]);
                mma_f16(acc[mf][nf], al[mf], bb[pr][sb], bb[pr][sb + 2]);
            }
        }
    }
}

// ---------------- epilogue ----------------
template <bool GELU, bool RES>
__device__ __forceinline__ void epilogue(float acc[4][4][4], int bm, int bn, int Nn,
                                         int wm, int wn, int lane,
                                         const float* bias, const float* res, float* out)
{
#pragma unroll
    for (int mf = 0; mf < 4; ++mf) {
#pragma unroll
        for (int nf = 0; nf < 4; ++nf) {
            const int n0 = bn + wn * 32 + nf * 8 + 2 * (lane & 3);
            const float b0 = __ldg(bias + n0), b1 = __ldg(bias + n0 + 1);
#pragma unroll
            for (int half = 0; half < 2; ++half) {
                const int m = bm + wm * 64 + mf * 16 + (lane >> 2) + half * 8;
                float v0 = acc[mf][nf][half * 2 + 0] + b0;
                float v1 = acc[mf][nf][half * 2 + 1] + b1;
                if (GELU) {
                    v0 = 0.5f * v0 * (1.f + erff(v0 * 0.70710678118f));
                    v1 = 0.5f * v1 * (1.f + erff(v1 * 0.70710678118f));
                }
                if (RES) {
                    float2 r2 = *(const float2*)(res + (size_t)m * Nn + n0);
                    v0 += r2.x; v1 += r2.y;
                }
                *(float2*)(out + (size_t)m * Nn + n0) = make_float2(v0, v1);
            }
        }
    }
}

// ---------------- dense GEMM: out = act(A @ B^T + bias) (+res) ----------------
template <bool GELU, bool RES>
__global__ void __launch_bounds__(256)
tc_gemm(const float* __restrict__ A, const __half* __restrict__ Bh,
        const float* __restrict__ bias, const float* __restrict__ res,
        float* __restrict__ out, int Nn, int Kk)
{
    extern __shared__ __align__(16) __half smem[];
    const int t = threadIdx.x, lane = t & 31, warp = t >> 5;
    const int wm = warp >> 2, wn = warp & 3;
    const int bm = blockIdx.y * 128, bn = blockIdx.x * 128;

    float acc[4][4][4];
#pragma unroll
    for (int a = 0; a < 4; ++a)
#pragma unroll
        for (int b = 0; b < 4; ++b)
#pragma unroll
            for (int c = 0; c < 4; ++c) acc[a][b][c] = 0.f;

    const int nchunk = Kk / 32;
    const int r0 = t >> 2, c0 = t & 3;
    const int r1 = (t + 256) >> 2;

    // preload chunk 0
    {
        const float* ap0 = A + (size_t)(bm + r0) * Kk + c0 * 8;
        const float* ap1 = A + (size_t)(bm + r1) * Kk + c0 * 8;
        uint4 h, l;
        cvt8h(*(const float4*)ap0, *(const float4*)(ap0 + 4), h, l);
        *(uint4*)(smem + SM_AHI + sidx(r0, c0 * 8)) = h;
        *(uint4*)(smem + SM_ALO + sidx(r0, c0 * 8)) = l;
        cvt8h(*(const float4*)ap1, *(const float4*)(ap1 + 4), h, l);
        *(uint4*)(smem + SM_AHI + sidx(r1, c0 * 8)) = h;
        *(uint4*)(smem + SM_ALO + sidx(r1, c0 * 8)) = l;
        *(uint4*)(smem + SM_B + sidx(r0, c0 * 8)) = *(const uint4*)(Bh + (size_t)(bn + r0) * Kk + c0 * 8);
        *(uint4*)(smem + SM_B + sidx(r1, c0 * 8)) = *(const uint4*)(Bh + (size_t)(bn + r1) * Kk + c0 * 8);
    }
    __syncthreads();

    for (int chunk = 0; chunk < nchunk; ++chunk) {
        const __half* cur = smem + (chunk & 1) * ST_STRIDE;
        __half* nxt = smem + ((chunk + 1) & 1) * ST_STRIDE;
        float4 pa[2][2]; uint4 pb[2];
        const bool more = (chunk + 1 < nchunk);
        if (more) {
            const int kb = (chunk + 1) * 32;
            const float* ap0 = A + (size_t)(bm + r0) * Kk + kb + c0 * 8;
            const float* ap1 = A + (size_t)(bm + r1) * Kk + kb + c0 * 8;
            pa[0][0] = *(const float4*)ap0; pa[0][1] = *(const float4*)(ap0 + 4);
            pa[1][0] = *(const float4*)ap1; pa[1][1] = *(const float4*)(ap1 + 4);
            pb[0] = *(const uint4*)(Bh + (size_t)(bn + r0) * Kk + kb + c0 * 8);
            pb[1] = *(const uint4*)(Bh + (size_t)(bn + r1) * Kk + kb + c0 * 8);
        }
        mma_chunk(cur, wm, wn, lane, acc);
        __syncthreads();
        if (more) {
            uint4 h, l;
            cvt8h(pa[0][0], pa[0][1], h, l);
            *(uint4*)(nxt + SM_AHI + sidx(r0, c0 * 8)) = h;
            *(uint4*)(nxt + SM_ALO + sidx(r0, c0 * 8)) = l;
            cvt8h(pa[1][0], pa[1][1], h, l);
            *(uint4*)(nxt + SM_AHI + sidx(r1, c0 * 8)) = h;
            *(uint4*)(nxt + SM_ALO + sidx(r1, c0 * 8)) = l;
            *(uint4*)(nxt + SM_B + sidx(r0, c0 * 8)) = pb[0];
            *(uint4*)(nxt + SM_B + sidx(r1, c0 * 8)) = pb[1];
        }
        __syncthreads();
    }
    epilogue<GELU, RES>(acc, bm, bn, Nn, wm, wn, lane, bias, res, out);
}

// ---------------- sparse CPE GEMM: scatter-accumulate per-tap tiles ----------------
__global__ void __launch_bounds__(256)
cpe_sparse(const float* __restrict__ feat, const __half* __restrict__ W,
           float* __restrict__ out)
{
    extern __shared__ __align__(16) __half smem[];
    __shared__ int sn[128];
    const int tile = blockIdx.y;
    if (tile >= g_ntiles) return;
    const int t = threadIdx.x, lane = t & 31, warp = t >> 5;
    const int wm = warp >> 2, wn = warp & 3;
    const int bn = blockIdx.x * 128;
    const int kk = g_tiletap[tile];
    const __half* Wk = W + (size_t)kk * C * C;
    const int2* pl = g_plist + (size_t)tile * 128;
    if (t < 128) sn[t] = pl[t].x;

    float acc[4][4][4];
#pragma unroll
    for (int a = 0; a < 4; ++a)
#pragma unroll
        for (int b = 0; b < 4; ++b)
#pragma unroll
            for (int c = 0; c < 4; ++c) acc[a][b][c] = 0.f;

    const int r0 = t >> 2, c0 = t & 3;
    const int r1 = (t + 256) >> 2;
    const int j0 = __ldg(&pl[r0].y), j1 = __ldg(&pl[r1].y);

    // preload chunk 0
    {
        float4 a00 = make_float4(0,0,0,0), a01 = a00, a10 = a00, a11 = a00;
        if (j0 >= 0) {
            const float* ap = feat + (size_t)j0 * C + c0 * 8;
            a00 = *(const float4*)ap; a01 = *(const float4*)(ap + 4);
        }
        if (j1 >= 0) {
            const float* ap = feat + (size_t)j1 * C + c0 * 8;
            a10 = *(const float4*)ap; a11 = *(const float4*)(ap + 4);
        }
        uint4 h, l;
        cvt8h(a00, a01, h, l);
        *(uint4*)(smem + SM_AHI + sidx(r0, c0 * 8)) = h;
        *(uint4*)(smem + SM_ALO + sidx(r0, c0 * 8)) = l;
        cvt8h(a10, a11, h, l);
        *(uint4*)(smem + SM_AHI + sidx(r1, c0 * 8)) = h;
        *(uint4*)(smem + SM_ALO + sidx(r1, c0 * 8)) = l;
        *(uint4*)(smem + SM_B + sidx(r0, c0 * 8)) = *(const uint4*)(Wk + (size_t)(bn + r0) * C + c0 * 8);
        *(uint4*)(smem + SM_B + sidx(r1, c0 * 8)) = *(const uint4*)(Wk + (size_t)(bn + r1) * C + c0 * 8);
    }
    __syncthreads();

    const int nchunk = C / 32;
    for (int chunk = 0; chunk < nchunk; ++chunk) {
        const __half* cur = smem + (chunk & 1) * ST_STRIDE;
        __half* nxt = smem + ((chunk + 1) & 1) * ST_STRIDE;
        float4 pa[2][2]; uint4 pb[2];
        const bool more = (chunk + 1 < nchunk);
        if (more) {
            const int kb = (chunk + 1) * 32;
            pa[0][0] = make_float4(0,0,0,0); pa[0][1] = pa[0][0];
            pa[1][0] = pa[0][0]; pa[1][1] = pa[0][0];
            if (j0 >= 0) {
                const float* ap = feat + (size_t)j0 * C + kb + c0 * 8;
                pa[0][0] = *(const float4*)ap; pa[0][1] = *(const float4*)(ap + 4);
            }
            if (j1 >= 0) {
                const float* ap = feat + (size_t)j1 * C + kb + c0 * 8;
                pa[1][0] = *(const float4*)ap; pa[1][1] = *(const float4*)(ap + 4);
            }
            pb[0] = *(const uint4*)(Wk + (size_t)(bn + r0) * C + kb + c0 * 8);
            pb[1] = *(const uint4*)(Wk + (size_t)(bn + r1) * C + kb + c0 * 8);
        }
        mma_chunk(cur, wm, wn, lane, acc);
        __syncthreads();
        if (more) {
            uint4 h, l;
            cvt8h(pa[0][0], pa[0][1], h, l);
            *(uint4*)(nxt + SM_AHI + sidx(r0, c0 * 8)) = h;
            *(uint4*)(nxt + SM_ALO + sidx(r0, c0 * 8)) = l;
            cvt8h(pa[1][0], pa[1][1], h, l);
            *(uint4*)(nxt + SM_AHI + sidx(r1, c0 * 8)) = h;
            *(uint4*)(nxt + SM_ALO + sidx(r1, c0 * 8)) = l;
            *(uint4*)(nxt + SM_B + sidx(r0, c0 * 8)) = pb[0];
            *(uint4*)(nxt + SM_B + sidx(r1, c0 * 8)) = pb[1];
        }
        __syncthreads();
    }
    // scatter-accumulate
#pragma unroll
    for (int mf = 0; mf < 4; ++mf) {
#pragma unroll
        for (int half = 0; half < 2; ++half) {
            const int ml = wm * 64 + mf * 16 + (lane >> 2) + half * 8;
            const int n = sn[ml];
            if (n < 0) continue;
            float* dst = out + (size_t)n * C;
#pragma unroll
            for (int nf = 0; nf < 4; ++nf) {
                const int n0 = bn + wn * 32 + nf * 8 + 2 * (lane & 3);
                atomicAdd(dst + n0,     acc[mf][nf][half * 2 + 0]);
                atomicAdd(dst + n0 + 1, acc[mf][nf][half * 2 + 1]);
            }
        }
    }
}

// ---------------- LayerNorm ----------------
__global__ void ln_kernel(const float* __restrict__ in, const float* __restrict__ res,
                          const float* __restrict__ gam, const float* __restrict__ bet,
                          float* __restrict__ out)
{
    const int n = blockIdx.x;
    const int t = threadIdx.x;
    float4 v = *(const float4*)(in + (size_t)n * C + t * 4);
    float s1 = v.x + v.y + v.z + v.w;
    float s2 = v.x * v.x + v.y * v.y + v.z * v.z + v.w * v.w;
#pragma unroll
    for (int o = 16; o; o >>= 1) {
        s1 += __shfl_xor_sync(0xffffffffu, s1, o);
        s2 += __shfl_xor_sync(0xffffffffu, s2, o);
    }
    __shared__ float sh1[4], sh2[4];
    const int wid = t >> 5, lane = t & 31;
    if (lane == 0) { sh1[wid] = s1; sh2[wid] = s2; }
    __syncthreads();
    float S1 = sh1[0] + sh1[1] + sh1[2] + sh1[3];
    float S2 = sh2[0] + sh2[1] + sh2[2] + sh2[3];
    float mean = S1 * (1.f / C);
    float var = S2 * (1.f / C) - mean * mean;
    float inv = rsqrtf(var + 1e-5f);
    float4 g4 = *(const float4*)(gam + t * 4);
    float4 b4 = *(const float4*)(bet + t * 4);
    float4 o4;
    o4.x = (v.x - mean) * inv * g4.x + b4.x;
    o4.y = (v.y - mean) * inv * g4.y + b4.y;
    o4.z = (v.z - mean) * inv * g4.z + b4.z;
    o4.w = (v.w - mean) * inv * g4.w + b4.w;
    if (res != nullptr) {
        float4 r4 = *(const float4*)(res + (size_t)n * C + t * 4);
        o4.x += r4.x; o4.y += r4.y; o4.z += r4.z; o4.w += r4.w;
    }
    *(float4*)(out + (size_t)n * C + t * 4) = o4;
}

// ---------------- tensor-core flash attention ----------------
#define ATT_Q 0
#define ATT_K 8192
#define ATT_V 16384
#define ATT_SMEM (24576 * 2)

__global__ void __launch_bounds__(256)
attn_kernel(const float* __restrict__ qkv, const int* __restrict__ order,
            float* __restrict__ o)
{
    extern __shared__ __align__(16) __half asmem[];
    const int t = threadIdx.x, lane = t & 31, warp = t >> 5;
    const int qt = blockIdx.x, h = blockIdx.y, p = blockIdx.z;
    const int qbase = p * KWIN + qt * 128;

    // load Q (scaled)
    for (int u = t; u < 1024; u += 256) {
        int r = u >> 3, c = u & 7;
        int n = __ldg(order + qbase + r);
        const float* src = qkv + (size_t)n * (3 * C) + h * HD + c * 8;
        float4 f0 = *(const float4*)src, f1 = *(const float4*)(src + 4);
        f0.x *= SCALE; f0.y *= SCALE; f0.z *= SCALE; f0.w *= SCALE;
        f1.x *= SCALE; f1.y *= SCALE; f1.z *= SCALE; f1.w *= SCALE;
        *(uint4*)(asmem + ATT_Q + aidx(r, c * 8)) = cvt8s(f0, f1);
    }

    float mrow[2] = {-1e30f, -1e30f}, lrow[2] = {0.f, 0.f};
    float oacc[8][4];
#pragma unroll
    for (int j = 0; j < 8; ++j)
#pragma unroll
        for (int c = 0; c < 4; ++c) oacc[j][c] = 0.f;

    for (int kt = 0; kt < KWIN / 128; ++kt) {
        __syncthreads();
        for (int u = t; u < 1024; u += 256) {
            int r = u >> 3, c = u & 7;
            int n = __ldg(order + p * KWIN + kt * 128 + r);
            const float* ks = qkv + (size_t)n * (3 * C) + C + h * HD + c * 8;
            const float* vs = qkv + (size_t)n * (3 * C) + 2 * C + h * HD + c * 8;
            *(uint4*)(asmem + ATT_K + aidx(r, c * 8)) =
                cvt8s(*(const float4*)ks, *(const float4*)(ks + 4));
            *(uint4*)(asmem + ATT_V + aidx(r, c * 8)) =
                cvt8s(*(const float4*)vs, *(const float4*)(vs + 4));
        }
        __syncthreads();

        // S = Q K^T (16 n8 tiles, fp32 accum)
        float s[16][4];
#pragma unroll
        for (int j = 0; j < 16; ++j)
#pragma unroll
            for (int c = 0; c < 4; ++c) s[j][c] = 0.f;
#pragma unroll
        for (int kk = 0; kk < 4; ++kk) {
            const int kc = kk * 2 + (lane >> 4);
            uint32_t a[4];
            {
                int row = warp * 16 + (lane & 15);
                ldmx4(a[0], a[1], a[2], a[3], s2u(asmem + ATT_Q + aidx(row, kc * 8)));
            }
#pragma unroll
            for (int np = 0; np < 8; ++np) {
                uint32_t b[4];
                int row = np * 16 + (lane & 15);
                ldmx4(b[0], b[1], b[2], b[3], s2u(asmem + ATT_K + aidx(row, kc * 8)));
                mma_f16(s[np * 2 + 0], a, b[0], b[2]);
                mma_f16(s[np * 2 + 1], a, b[1], b[3]);
            }
        }

        // online softmax (per row-half), P in fp16 via h2exp2
        uint32_t ph[16][2];
#pragma unroll
        for (int half = 0; half < 2; ++half) {
            float mx = mrow[half];
#pragma unroll
            for (int j = 0; j < 16; ++j)
                mx = fmaxf(mx, fmaxf(s[j][half * 2], s[j][half * 2 + 1]));
            mx = fmaxf(mx, __shfl_xor_sync(0xffffffffu, mx, 1));
            mx = fmaxf(mx, __shfl_xor_sync(0xffffffffu, mx, 2));
            const float alpha = __expf(mrow[half] - mx);
            float sum = 0.f;
#pragma unroll
            for (int j = 0; j < 16; ++j) {
                __half2 e = h2exp2(__floats2half2_rn(
                    (s[j][half * 2] - mx) * 1.44269504f,
                    (s[j][half * 2 + 1] - mx) * 1.44269504f));
                ph[j][half] = h2u(e);
                float2 f = __half22float2(e);
                sum += f.x + f.y;
            }
            sum += __shfl_xor_sync(0xffffffffu, sum, 1);
            sum += __shfl_xor_sync(0xffffffffu, sum, 2);
            lrow[half] = lrow[half] * alpha + sum;
            mrow[half] = mx;
#pragma unroll
            for (int j = 0; j < 8; ++j) {
                oacc[j][half * 2] *= alpha;
                oacc[j][half * 2 + 1] *= alpha;
            }
        }

        // O += P V
#pragma unroll
        for (int kc = 0; kc < 8; ++kc) {
            uint32_t pa[4] = { ph[kc * 2][0], ph[kc * 2][1], ph[kc * 2 + 1][0], ph[kc * 2 + 1][1] };
#pragma unroll
            for (int dp = 0; dp < 4; ++dp) {
                uint32_t b[4];
                int row = kc * 16 + ((lane >> 3) & 1) * 8 + (lane & 7);
                int col = dp * 16 + (lane >> 4) * 8;
                ldmx4t(b[0], b[1], b[2], b[3], s2u(asmem + ATT_V + aidx(row, col)));
                mma_f16(oacc[dp * 2 + 0], pa, b[0], b[1]);
                mma_f16(oacc[dp * 2 + 1], pa, b[2], b[3]);
            }
        }
    }

    // write out
#pragma unroll
    for (int half = 0; half < 2; ++half) {
        const float inv = 1.f / lrow[half];
        const int r = warp * 16 + (lane >> 2) + half * 8;
        const int n = __ldg(order + qbase + r);
        float* dst = o + (size_t)n * C + h * HD;
#pragma unroll
        for (int j = 0; j < 8; ++j) {
            const int d0 = j * 8 + 2 * (lane & 3);
            *(float2*)(dst + d0) = make_float2(oacc[j][half * 2] * inv,
                                               oacc[j][half * 2 + 1] * inv);
        }
    }
}

// ---------------- launch ----------------
extern "C" void kernel_launch(void* const* d_in, const int* in_sizes, int n_in,
                              void* d_out, int out_size)
{
    const float* feat      = (const float*)d_in[0];
    const int*   nbr       = (const int*)d_in[1];
    const int*   order     = (const int*)d_in[2];
    const float* cpe_w     = (const float*)d_in[3];
    const float* cpe_b     = (const float*)d_in[4];
    const float* cpe_lin_w = (const float*)d_in[5];
    const float* cpe_lin_b = (const float*)d_in[6];
    const float* cpe_ln_g  = (const float*)d_in[7];
    const float* cpe_ln_b  = (const float*)d_in[8];
    const float* ln1_g     = (const float*)d_in[9];
    const float* ln1_b     = (const float*)d_in[10];
    const float* qkv_w     = (const float*)d_in[11];
    const float* qkv_b     = (const float*)d_in[12];
    const float* proj_w    = (const float*)d_in[13];
    const float* proj_b    = (const float*)d_in[14];
    const float* ln2_g     = (const float*)d_in[15];
    const float* ln2_b     = (const float*)d_in[16];
    const float* fc1_w     = (const float*)d_in[17];
    const float* fc1_b     = (const float*)d_in[18];
    const float* fc2_w     = (const float*)d_in[19];
    const float* fc2_b     = (const float*)d_in[20];
    float* out = (float*)d_out;

    float *tmp1, *tmp2, *feat1, *x, *qkvb, *ob, *y;
    __half* wh;
    cudaGetSymbolAddress((void**)&tmp1,  g_tmp1);
    cudaGetSymbolAddress((void**)&tmp2,  g_tmp2);
    cudaGetSymbolAddress((void**)&feat1, g_feat1);
    cudaGetSymbolAddress((void**)&x,     g_x);
    cudaGetSymbolAddress((void**)&qkvb,  g_qkv);
    cudaGetSymbolAddress((void**)&ob,    g_o);
    cudaGetSymbolAddress((void**)&y,     g_y);
    cudaGetSymbolAddress((void**)&wh,    g_wh);

    cudaFuncSetAttribute(tc_gemm<false,false>, cudaFuncAttributeMaxDynamicSharedMemorySize, SMEM_BYTES);
    cudaFuncSetAttribute(tc_gemm<false,true>,  cudaFuncAttributeMaxDynamicSharedMemorySize, SMEM_BYTES);
    cudaFuncSetAttribute(tc_gemm<true,false>,  cudaFuncAttributeMaxDynamicSharedMemorySize, SMEM_BYTES);
    cudaFuncSetAttribute(cpe_sparse,           cudaFuncAttributeMaxDynamicSharedMemorySize, SMEM_BYTES);
    cudaFuncSetAttribute(attn_kernel,          cudaFuncAttributeMaxDynamicSharedMemorySize, ATT_SMEM);

    // weight fp16 prepass
    {
        struct { const float* s; int off; int n; } ws[6] = {
            { cpe_w,     OFF_CPE,  27*C*C },
            { cpe_lin_w, OFF_LIN,  C*C },
            { qkv_w,     OFF_QKV,  3*C*C },
            { proj_w,    OFF_PROJ, C*C },
            { fc1_w,     OFF_FC1,  4*C*C },
            { fc2_w,     OFF_FC2,  4*C*C },
        };
        for (int i = 0; i < 6; ++i)
            w_prep<<<(ws[i].n / 8 + 255) / 256, 256>>>(ws[i].s, wh + ws[i].off, ws[i].n);
    }

    // sparse CPE prepass
    prep_zero<<<512, 256>>>();
    prep_count<<<dim3(NPTS / 256, 26), 256>>>(nbr);
    prep_scan<<<1, 128>>>();
    prep_fill<<<dim3(NPTS / 256, 26), 256>>>(nbr);

    const int MB = NPTS / 128;  // 128
    // 1) CPE: center tap dense (writes bias), then 26 sparse taps scatter-add
    tc_gemm<false,false><<<dim3(C/128, MB), 256, SMEM_BYTES>>>(
        feat, wh + OFF_CPE + (size_t)13*C*C, cpe_b, nullptr, tmp1, C, C);
    cpe_sparse<<<dim3(C/128, MAX_TILES), 256, SMEM_BYTES>>>(feat, wh + OFF_CPE, tmp1);
    // 2) cpe_lin
    tc_gemm<false,false><<<dim3(C/128, MB), 256, SMEM_BYTES>>>(tmp1, wh + OFF_LIN, cpe_lin_b, nullptr, tmp2, C, C);
    // 3) feat1 = feat + LN(tmp2)
    ln_kernel<<<NPTS, 128>>>(tmp2, feat, cpe_ln_g, cpe_ln_b, feat1);
    // 4) x = LN(feat1)
    ln_kernel<<<NPTS, 128>>>(feat1, nullptr, ln1_g, ln1_b, x);
    // 5) qkv
    tc_gemm<false,false><<<dim3(3*C/128, MB), 256, SMEM_BYTES>>>(x, wh + OFF_QKV, qkv_b, nullptr, qkvb, 3*C, C);
    // 6) attention
    attn_kernel<<<dim3(KWIN/128, H, P), 256, ATT_SMEM>>>(qkvb, order, ob);
    // 7) feat2 = feat1 + proj(ob) -> tmp1
    tc_gemm<false,true><<<dim3(C/128, MB), 256, SMEM_BYTES>>>(ob, wh + OFF_PROJ, proj_b, feat1, tmp1, C, C);
    // 8) x = LN(feat2)
    ln_kernel<<<NPTS, 128>>>(tmp1, nullptr, ln2_g, ln2_b, x);
    // 9) y = gelu(fc1(x))
    tc_gemm<true,false><<<dim3(4*C/128, MB), 256, SMEM_BYTES>>>(x, wh + OFF_FC1, fc1_b, nullptr, y, 4*C, C);
    // 10) out = feat2 + fc2(y)
    tc_gemm<false,true><<<dim3(C/128, MB), 256, SMEM_BYTES>>>(y, wh + OFF_FC2, fc2_b, tmp1, out, C, 4*C);
}